// round 1
// baseline (speedup 1.0000x reference)
#include <cuda_runtime.h>
#include <math.h>

#define B_ 4
#define L_ 1024
#define D_ 1024
#define H_ 16
#define DK 64

// Scratch (device globals; no allocation allowed)
__device__ float g_q[B_*H_*L_*DK];
__device__ float g_k[B_*H_*L_*DK];
__device__ float g_v[B_*H_*L_*DK];
__device__ float g_ctx[B_*H_*L_*DK];
__device__ float g_bias[B_*L_*L_];
__device__ float g_proj[B_*L_*H_];

__device__ __forceinline__ int clampi(int v, int lo, int hi){
    return v < lo ? lo : (v > hi ? hi : v);
}

// proj[b,i,h] = sum_s ss[b,i,s] * ssw[h,s]
__global__ void proj_kernel(const float* __restrict__ ss, const float* __restrict__ ssw){
    int gid = blockIdx.x * 256 + threadIdx.x;   // B*L*H = 65536
    int ih = gid >> 4;   // b*L + i
    int h  = gid & 15;
    float acc = 0.f;
    #pragma unroll
    for (int s = 0; s < 8; s++) acc += ss[ih*8 + s] * ssw[h*8 + s];
    g_proj[gid] = acc;
}

// bias_base[b,i,j] = dist_pen + inter + struct  (head-independent part)
__global__ void bias_kernel(const float* __restrict__ pf, const int* __restrict__ aa,
                            const float* __restrict__ inter_mat,
                            const float* __restrict__ ps_p, const float* __restrict__ dd_p){
    __shared__ float s_inter[625];
    __shared__ float s_pi[16];
    int tid = threadIdx.x;
    int bi = blockIdx.x;            // b*L + i
    int b = bi >> 10, i = bi & 1023;
    for (int t = tid; t < 625; t += 256) s_inter[t] = inter_mat[t];
    if (tid < 16) s_pi[tid] = g_proj[bi*16 + tid];
    __syncthreads();

    float sigps = 1.f / (1.f + __expf(-ps_p[0]));
    float decay = fminf(fmaxf(dd_p[0], 0.1f), 5.0f);
    int ai = clampi(aa[bi], 0, 24);
    float pi[16];
    #pragma unroll
    for (int s = 0; s < 16; s++) pi[s] = s_pi[s];
    const float* projb = g_proj + (b << 10) * 16;
    int base = (b << 20) + (i << 10);

    for (int jj = 0; jj < 4; jj++){
        int j = tid + (jj << 8);
        float d = pf[base + j];
        d = fminf(fmaxf(d, 0.1f), 50.0f);
        float pen = -powf(d, decay) * sigps;
        int aj = clampi(aa[(b << 10) + j], 0, 24);
        float sym = 0.5f * (s_inter[ai*25 + aj] + s_inter[aj*25 + ai]);
        float interv = sym / (1.0f + fabsf((float)(j - i)));
        const float* pj = projb + j*16;
        float dot = 0.f;
        #pragma unroll
        for (int s = 0; s < 16; s++) dot += pi[s] * pj[s];
        float st = 1.f / (1.f + __expf(-dot)) - 0.5f;
        g_bias[base + j] = pen + interv + st;
    }
}

// C = x @ W^T, stored as (B,H,L,dk). M=4096, N=1024, K=1024.
__global__ void __launch_bounds__(256) qkv_gemm(const float* __restrict__ x,
        const float* __restrict__ Wq, const float* __restrict__ Wk, const float* __restrict__ Wv){
    const float* W; float* out;
    if (blockIdx.z == 0)      { W = Wq; out = g_q; }
    else if (blockIdx.z == 1) { W = Wk; out = g_k; }
    else                      { W = Wv; out = g_v; }

    __shared__ float As[16][128];
    __shared__ float Bs[16][128];
    int tid = threadIdx.x;
    int m0 = blockIdx.y << 7, n0 = blockIdx.x << 7;
    int ty = tid >> 4, tx = tid & 15;
    float acc[8][8] = {};

    for (int k0 = 0; k0 < 1024; k0 += 16){
        #pragma unroll
        for (int l = 0; l < 2; l++){
            int id = tid + (l << 8);
            int row = id >> 2, kq = (id & 3) << 2;
            float4 a = *(const float4*)(x + (m0 + row)*1024 + k0 + kq);
            As[kq+0][row] = a.x; As[kq+1][row] = a.y; As[kq+2][row] = a.z; As[kq+3][row] = a.w;
            float4 bb = *(const float4*)(W + (n0 + row)*1024 + k0 + kq);
            Bs[kq+0][row] = bb.x; Bs[kq+1][row] = bb.y; Bs[kq+2][row] = bb.z; Bs[kq+3][row] = bb.w;
        }
        __syncthreads();
        #pragma unroll
        for (int kk = 0; kk < 16; kk++){
            float4 a0 = *(float4*)&As[kk][ty << 3];
            float4 a1 = *(float4*)&As[kk][(ty << 3) + 4];
            float4 b0 = *(float4*)&Bs[kk][tx << 3];
            float4 b1 = *(float4*)&Bs[kk][(tx << 3) + 4];
            float av[8] = {a0.x,a0.y,a0.z,a0.w,a1.x,a1.y,a1.z,a1.w};
            float bv[8] = {b0.x,b0.y,b0.z,b0.w,b1.x,b1.y,b1.z,b1.w};
            #pragma unroll
            for (int ii = 0; ii < 8; ii++)
                #pragma unroll
                for (int jj = 0; jj < 8; jj++)
                    acc[ii][jj] += av[ii] * bv[jj];
        }
        __syncthreads();
    }
    #pragma unroll
    for (int ii = 0; ii < 8; ii++){
        int m = m0 + (ty << 3) + ii;
        int b = m >> 10, l = m & 1023;
        #pragma unroll
        for (int jj = 0; jj < 8; jj++){
            int n = n0 + (tx << 3) + jj;
            int h = n >> 6, dd = n & 63;
            out[(((b << 4) + h) << 16) + (l << 6) + dd] = acc[ii][jj];
        }
    }
}

// Flash attention per (b,h, 64-query tile); bias from g_bias + dist_bias[h].
__global__ void __launch_bounds__(256) attn_kernel(const float* __restrict__ dist_bias){
    extern __shared__ float smbuf[];
    float* sq = smbuf;              // 64*68
    float* sk = smbuf + 64*68;
    float* sv = smbuf + 2*64*68;
    float* sp = smbuf + 3*64*68;

    int b = blockIdx.z, h = blockIdx.y, it = blockIdx.x;
    int i0 = it << 6;
    int tid = threadIdx.x;
    int ty = tid >> 4, tx = tid & 15;
    const float* qb = g_q + (((b << 4) + h) << 16);
    const float* kb = g_k + (((b << 4) + h) << 16);
    const float* vb = g_v + (((b << 4) + h) << 16);
    const float* biasb = g_bias + (b << 20) + (i0 << 10);
    float db = dist_bias[h];

    // load Q tile
    #pragma unroll
    for (int l = 0; l < 4; l++){
        int id = tid + (l << 8);
        int row = id >> 4, dc = (id & 15) << 2;
        *(float4*)&sq[row*68 + dc] = *(const float4*)(qb + ((i0 + row) << 6) + dc);
    }

    float m_r[4], l_r[4], acc[4][4];
    #pragma unroll
    for (int r = 0; r < 4; r++){
        m_r[r] = -INFINITY; l_r[r] = 0.f;
        #pragma unroll
        for (int c = 0; c < 4; c++) acc[r][c] = 0.f;
    }

    for (int jt = 0; jt < 16; jt++){
        int j0 = jt << 6;
        __syncthreads();    // protect sk/sv/sp from previous iteration readers
        #pragma unroll
        for (int l = 0; l < 4; l++){
            int id = tid + (l << 8);
            int row = id >> 4, dc = (id & 15) << 2;
            *(float4*)&sk[row*68 + dc] = *(const float4*)(kb + ((j0 + row) << 6) + dc);
            *(float4*)&sv[row*68 + dc] = *(const float4*)(vb + ((j0 + row) << 6) + dc);
        }
        __syncthreads();

        // S = Q K^T (4x4 per thread)
        float s[4][4] = {};
        #pragma unroll
        for (int dc = 0; dc < 16; dc++){
            float qv[16], kv[16];
            #pragma unroll
            for (int r = 0; r < 4; r++)
                *(float4*)&qv[r*4] = *(float4*)&sq[((ty << 2) + r)*68 + (dc << 2)];
            #pragma unroll
            for (int c = 0; c < 4; c++)
                *(float4*)&kv[c*4] = *(float4*)&sk[((tx << 2) + c)*68 + (dc << 2)];
            #pragma unroll
            for (int r = 0; r < 4; r++)
                #pragma unroll
                for (int c = 0; c < 4; c++)
                    #pragma unroll
                    for (int e = 0; e < 4; e++)
                        s[r][c] += qv[r*4 + e] * kv[c*4 + e];
        }

        // scale + bias
        #pragma unroll
        for (int r = 0; r < 4; r++){
            float4 bv = *(const float4*)(biasb + (((ty << 2) + r) << 10) + j0 + (tx << 2));
            s[r][0] = s[r][0]*0.125f + bv.x + db;
            s[r][1] = s[r][1]*0.125f + bv.y + db;
            s[r][2] = s[r][2]*0.125f + bv.z + db;
            s[r][3] = s[r][3]*0.125f + bv.w + db;
        }

        // online softmax (rows shared by 16 lanes)
        #pragma unroll
        for (int r = 0; r < 4; r++){
            float mx = fmaxf(fmaxf(s[r][0], s[r][1]), fmaxf(s[r][2], s[r][3]));
            #pragma unroll
            for (int off = 1; off < 16; off <<= 1)
                mx = fmaxf(mx, __shfl_xor_sync(0xffffffffu, mx, off));
            float mnew = fmaxf(m_r[r], mx);
            float corr = __expf(m_r[r] - mnew);
            float psum = 0.f;
            #pragma unroll
            for (int c = 0; c < 4; c++){
                s[r][c] = __expf(s[r][c] - mnew);
                psum += s[r][c];
            }
            #pragma unroll
            for (int off = 1; off < 16; off <<= 1)
                psum += __shfl_xor_sync(0xffffffffu, psum, off);
            l_r[r] = l_r[r]*corr + psum;
            m_r[r] = mnew;
            #pragma unroll
            for (int c = 0; c < 4; c++) acc[r][c] *= corr;
            *(float4*)&sp[((ty << 2) + r)*68 + (tx << 2)] =
                make_float4(s[r][0], s[r][1], s[r][2], s[r][3]);
        }
        __syncthreads();

        // acc += P V
        #pragma unroll
        for (int jc = 0; jc < 16; jc++){
            float pv[16], vv[16];
            #pragma unroll
            for (int r = 0; r < 4; r++)
                *(float4*)&pv[r*4] = *(float4*)&sp[((ty << 2) + r)*68 + (jc << 2)];
            #pragma unroll
            for (int j = 0; j < 4; j++)
                *(float4*)&vv[j*4] = *(float4*)&sv[((jc << 2) + j)*68 + (tx << 2)];
            #pragma unroll
            for (int r = 0; r < 4; r++)
                #pragma unroll
                for (int c = 0; c < 4; c++)
                    #pragma unroll
                    for (int j = 0; j < 4; j++)
                        acc[r][c] += pv[r*4 + j] * vv[j*4 + c];
        }
    }

    // write ctx
    #pragma unroll
    for (int r = 0; r < 4; r++){
        float inv = 1.f / l_r[r];
        float4 o = make_float4(acc[r][0]*inv, acc[r][1]*inv, acc[r][2]*inv, acc[r][3]*inv);
        *(float4*)(g_ctx + (((b << 4) + h) << 16) + ((i0 + (ty << 2) + r) << 6) + (tx << 2)) = o;
    }
}

// out = ctx @ Wo^T + bo, ctx gathered from (B,H,L,dk)
__global__ void __launch_bounds__(256) out_gemm(const float* __restrict__ Wo,
        const float* __restrict__ bo, float* __restrict__ out){
    __shared__ float As[16][128];
    __shared__ float Bs[16][128];
    int tid = threadIdx.x;
    int m0 = blockIdx.y << 7, n0 = blockIdx.x << 7;
    int ty = tid >> 4, tx = tid & 15;
    float acc[8][8] = {};

    for (int k0 = 0; k0 < 1024; k0 += 16){
        #pragma unroll
        for (int l = 0; l < 2; l++){
            int id = tid + (l << 8);
            int row = id >> 2, kq = (id & 3) << 2;
            int m = m0 + row; int b = m >> 10, li = m & 1023;
            int c = k0 + kq;  int h = c >> 6, dd = c & 63;
            float4 a = *(const float4*)(g_ctx + (((b << 4) + h) << 16) + (li << 6) + dd);
            As[kq+0][row] = a.x; As[kq+1][row] = a.y; As[kq+2][row] = a.z; As[kq+3][row] = a.w;
            float4 bb = *(const float4*)(Wo + (n0 + row)*1024 + k0 + kq);
            Bs[kq+0][row] = bb.x; Bs[kq+1][row] = bb.y; Bs[kq+2][row] = bb.z; Bs[kq+3][row] = bb.w;
        }
        __syncthreads();
        #pragma unroll
        for (int kk = 0; kk < 16; kk++){
            float4 a0 = *(float4*)&As[kk][ty << 3];
            float4 a1 = *(float4*)&As[kk][(ty << 3) + 4];
            float4 b0 = *(float4*)&Bs[kk][tx << 3];
            float4 b1 = *(float4*)&Bs[kk][(tx << 3) + 4];
            float av[8] = {a0.x,a0.y,a0.z,a0.w,a1.x,a1.y,a1.z,a1.w};
            float bv[8] = {b0.x,b0.y,b0.z,b0.w,b1.x,b1.y,b1.z,b1.w};
            #pragma unroll
            for (int ii = 0; ii < 8; ii++)
                #pragma unroll
                for (int jj = 0; jj < 8; jj++)
                    acc[ii][jj] += av[ii] * bv[jj];
        }
        __syncthreads();
    }
    #pragma unroll
    for (int ii = 0; ii < 8; ii++){
        int m = m0 + (ty << 3) + ii;
        #pragma unroll
        for (int jj = 0; jj < 8; jj++){
            int n = n0 + (tx << 3) + jj;
            out[m*1024 + n] = acc[ii][jj] + bo[n];
        }
    }
}

extern "C" void kernel_launch(void* const* d_in, const int* in_sizes, int n_in,
                              void* d_out, int out_size){
    const float* x         = (const float*)d_in[0];
    const float* pf        = (const float*)d_in[1];
    const int*   aa        = (const int*)  d_in[2];
    const float* ss        = (const float*)d_in[3];
    const float* Wq        = (const float*)d_in[4];
    const float* Wk        = (const float*)d_in[5];
    const float* Wv        = (const float*)d_in[6];
    const float* Wo        = (const float*)d_in[7];
    const float* bo        = (const float*)d_in[8];
    const float* dist_bias = (const float*)d_in[9];
    const float* inter_mat = (const float*)d_in[10];
    const float* ssw       = (const float*)d_in[11];
    const float* ps        = (const float*)d_in[12];
    const float* dd        = (const float*)d_in[13];
    float* out = (float*)d_out;

    proj_kernel<<<256, 256>>>(ss, ssw);
    bias_kernel<<<4096, 256>>>(pf, aa, inter_mat, ps, dd);

    dim3 gq(8, 32, 3);
    qkv_gemm<<<gq, 256>>>(x, Wq, Wk, Wv);

    int attn_smem = 4 * 64 * 68 * sizeof(float);  // 69632 B
    cudaFuncSetAttribute(attn_kernel, cudaFuncAttributeMaxDynamicSharedMemorySize, attn_smem);
    dim3 ga(16, 16, 4);
    attn_kernel<<<ga, 256, attn_smem>>>(dist_bias);

    dim3 go(8, 32, 1);
    out_gemm<<<go, 256>>>(Wo, bo, out);
}

// round 6
// speedup vs baseline: 1.7959x; 1.7959x over previous
#include <cuda_runtime.h>
#include <cuda_bf16.h>
#include <math.h>

#define B_ 4
#define L_ 1024
#define H_ 16
#define DK 64

// Scratch (device globals; no allocation allowed)
__device__ float g_q[B_*H_*L_*DK];
__device__ float g_k[B_*H_*L_*DK];
__device__ float g_v[B_*H_*L_*DK];
__device__ float g_ctx[B_*H_*L_*DK];
__device__ float g_bias[B_*L_*L_];
__device__ float g_proj[B_*L_*H_];

__device__ __forceinline__ int clampi(int v, int lo, int hi){
    return v < lo ? lo : (v > hi ? hi : v);
}

// Split an fp32 pair into packed bf16x2 hi and lo words (little-endian: .x low).
__device__ __forceinline__ void split2(float x, float y, unsigned& hiw, unsigned& low){
    __nv_bfloat16 hx = __float2bfloat16(x);
    __nv_bfloat16 hy = __float2bfloat16(y);
    float rx = x - __bfloat162float(hx);
    float ry = y - __bfloat162float(hy);
    __nv_bfloat162 h; h.x = hx; h.y = hy;
    __nv_bfloat162 l = __floats2bfloat162_rn(rx, ry);
    hiw = *(unsigned*)&h;
    low = *(unsigned*)&l;
}

// m16n8k16 bf16 mma, f32 accumulate
__device__ __forceinline__ void mma_bf16(float* c, const unsigned* a, const unsigned* b){
    asm volatile(
        "mma.sync.aligned.m16n8k16.row.col.f32.bf16.bf16.f32 "
        "{%0,%1,%2,%3},{%4,%5,%6,%7},{%8,%9},{%0,%1,%2,%3};"
        : "+f"(c[0]), "+f"(c[1]), "+f"(c[2]), "+f"(c[3])
        : "r"(a[0]), "r"(a[1]), "r"(a[2]), "r"(a[3]), "r"(b[0]), "r"(b[1]));
}

// proj[b,i,h] = sum_s ss[b,i,s] * ssw[h,s]
__global__ void proj_kernel(const float* __restrict__ ss, const float* __restrict__ ssw){
    int gid = blockIdx.x * 256 + threadIdx.x;   // B*L*H = 65536
    int ih = gid >> 4;
    int h  = gid & 15;
    float acc = 0.f;
    #pragma unroll
    for (int s = 0; s < 8; s++) acc += ss[ih*8 + s] * ssw[h*8 + s];
    g_proj[gid] = acc;
}

// bias_base[b,i,j] = dist_pen + inter + struct  (head-independent part)
__global__ void bias_kernel(const float* __restrict__ pf, const int* __restrict__ aa,
                            const float* __restrict__ inter_mat,
                            const float* __restrict__ ps_p, const float* __restrict__ dd_p){
    __shared__ float s_inter[625];
    __shared__ float s_pi[16];
    int tid = threadIdx.x;
    int bi = blockIdx.x;            // b*L + i
    int b = bi >> 10, i = bi & 1023;
    for (int t = tid; t < 625; t += 256) s_inter[t] = inter_mat[t];
    if (tid < 16) s_pi[tid] = g_proj[bi*16 + tid];
    __syncthreads();

    float sigps = 1.f / (1.f + __expf(-ps_p[0]));
    float decay = fminf(fmaxf(dd_p[0], 0.1f), 5.0f);
    int ai = clampi(aa[bi], 0, 24);
    float pi[16];
    #pragma unroll
    for (int s = 0; s < 16; s++) pi[s] = s_pi[s];
    const float* projb = g_proj + (b << 10) * 16;
    int base = (b << 20) + (i << 10);

    for (int jj = 0; jj < 4; jj++){
        int j = tid + (jj << 8);
        float d = pf[base + j];
        d = fminf(fmaxf(d, 0.1f), 50.0f);
        float pen = -__powf(d, decay) * sigps;
        int aj = clampi(aa[(b << 10) + j], 0, 24);
        float sym = 0.5f * (s_inter[ai*25 + aj] + s_inter[aj*25 + ai]);
        float interv = sym / (1.0f + fabsf((float)(j - i)));
        const float* pj = projb + j*16;
        float dot = 0.f;
        #pragma unroll
        for (int s = 0; s < 16; s++) dot += pi[s] * pj[s];
        float st = 1.f / (1.f + __expf(-dot)) - 0.5f;
        g_bias[base + j] = pen + interv + st;
    }
}

// ---------------------------------------------------------------------------
// bf16x3 tensor GEMM: C = x @ W^T, stored to (B,H,L,dk). M=4096,N=1024,K=1024
// CTA 128x128, 8 warps (2x4), warp tile 64x32, k-step 16, double-buffered.
// smem word layout: [row][kp] (kp = packed bf16x2 along k), stride 9 words.
// ---------------------------------------------------------------------------
__global__ void __launch_bounds__(256,2) qkv_gemm_b3(const float* __restrict__ x,
        const float* __restrict__ Wq, const float* __restrict__ Wk, const float* __restrict__ Wv){
    __shared__ unsigned Ah[2][1152], Al[2][1152];   // 128 * 9
    __shared__ unsigned Bh[2][1152], Bl[2][1152];
    const float* W; float* out;
    if (blockIdx.z == 0)      { W = Wq; out = g_q; }
    else if (blockIdx.z == 1) { W = Wk; out = g_k; }
    else                      { W = Wv; out = g_v; }

    int tid = threadIdx.x;
    int warp = tid >> 5, lane = tid & 31;
    int g = lane >> 2, tg = lane & 3;
    int wm = warp >> 2, wn = warp & 3;
    int m0 = blockIdx.y << 7, n0 = blockIdx.x << 7;

    float acc[4][4][4];
    #pragma unroll
    for (int a = 0; a < 4; a++)
        #pragma unroll
        for (int bq = 0; bq < 4; bq++)
            #pragma unroll
            for (int c = 0; c < 4; c++) acc[a][bq][c] = 0.f;

    // stage 0
    #pragma unroll
    for (int l = 0; l < 2; l++){
        int id = tid + (l << 8);
        int row = id >> 2, kq = (id & 3) << 2, kp = (id & 3) << 1;
        float4 a = *(const float4*)(x + (m0 + row)*1024 + kq);
        unsigned h0,l0,h1,l1;
        split2(a.x, a.y, h0, l0); split2(a.z, a.w, h1, l1);
        Ah[0][row*9 + kp] = h0; Ah[0][row*9 + kp + 1] = h1;
        Al[0][row*9 + kp] = l0; Al[0][row*9 + kp + 1] = l1;
        float4 bb = *(const float4*)(W + (n0 + row)*1024 + kq);
        split2(bb.x, bb.y, h0, l0); split2(bb.z, bb.w, h1, l1);
        Bh[0][row*9 + kp] = h0; Bh[0][row*9 + kp + 1] = h1;
        Bl[0][row*9 + kp] = l0; Bl[0][row*9 + kp + 1] = l1;
    }
    __syncthreads();

    int s = 0;
    for (int kt = 0; kt < 64; kt++){
        float4 pa[2], pb[2];
        if (kt < 63){
            int k0n = (kt + 1) << 4;
            #pragma unroll
            for (int l = 0; l < 2; l++){
                int id = tid + (l << 8);
                int row = id >> 2, kq = (id & 3) << 2;
                pa[l] = *(const float4*)(x + (m0 + row)*1024 + k0n + kq);
                pb[l] = *(const float4*)(W + (n0 + row)*1024 + k0n + kq);
            }
        }

        unsigned bh[4][2], bl_[4][2];
        #pragma unroll
        for (int nt = 0; nt < 4; nt++){
            int nb = (wn << 5) + (nt << 3) + g;
            bh[nt][0]  = Bh[s][nb*9 + tg];     bh[nt][1]  = Bh[s][nb*9 + tg + 4];
            bl_[nt][0] = Bl[s][nb*9 + tg];     bl_[nt][1] = Bl[s][nb*9 + tg + 4];
        }
        #pragma unroll
        for (int mt = 0; mt < 4; mt++){
            int rb = (wm << 6) + (mt << 4);
            unsigned ah[4], al_[4];
            ah[0]  = Ah[s][(rb + g    )*9 + tg];     ah[1]  = Ah[s][(rb + g + 8)*9 + tg];
            ah[2]  = Ah[s][(rb + g    )*9 + tg + 4]; ah[3]  = Ah[s][(rb + g + 8)*9 + tg + 4];
            al_[0] = Al[s][(rb + g    )*9 + tg];     al_[1] = Al[s][(rb + g + 8)*9 + tg];
            al_[2] = Al[s][(rb + g    )*9 + tg + 4]; al_[3] = Al[s][(rb + g + 8)*9 + tg + 4];
            #pragma unroll
            for (int nt = 0; nt < 4; nt++){
                mma_bf16(acc[mt][nt], ah,  bh[nt]);
                mma_bf16(acc[mt][nt], ah,  bl_[nt]);
                mma_bf16(acc[mt][nt], al_, bh[nt]);
            }
        }

        if (kt < 63){
            #pragma unroll
            for (int l = 0; l < 2; l++){
                int id = tid + (l << 8);
                int row = id >> 2, kp = (id & 3) << 1;
                unsigned h0,l0,h1,l1;
                split2(pa[l].x, pa[l].y, h0, l0); split2(pa[l].z, pa[l].w, h1, l1);
                Ah[s^1][row*9 + kp] = h0; Ah[s^1][row*9 + kp + 1] = h1;
                Al[s^1][row*9 + kp] = l0; Al[s^1][row*9 + kp + 1] = l1;
                split2(pb[l].x, pb[l].y, h0, l0); split2(pb[l].z, pb[l].w, h1, l1);
                Bh[s^1][row*9 + kp] = h0; Bh[s^1][row*9 + kp + 1] = h1;
                Bl[s^1][row*9 + kp] = l0; Bl[s^1][row*9 + kp + 1] = l1;
            }
        }
        __syncthreads();
        s ^= 1;
    }

    // epilogue: scatter to (B,H,L,dk). c0,c1 = row g; c2,c3 = row g+8
    #pragma unroll
    for (int mt = 0; mt < 4; mt++){
        #pragma unroll
        for (int nt = 0; nt < 4; nt++){
            int m = m0 + (wm << 6) + (mt << 4) + g;
            int n = n0 + (wn << 5) + (nt << 3) + (tg << 1);
            int b = m >> 10, li = m & 1023;
            int h = n >> 6, dd = n & 63;
            float* p0 = out + ((((b << 4) + h) << 16) + (li << 6) + dd);
            *(float2*)p0 = make_float2(acc[mt][nt][0], acc[mt][nt][1]);
            float* p1 = out + ((((b << 4) + h) << 16) + ((li + 8) << 6) + dd);
            *(float2*)p1 = make_float2(acc[mt][nt][2], acc[mt][nt][3]);
        }
    }
}

// out = ctx @ Wo^T + bo, ctx gathered from (B,H,L,dk)
__global__ void __launch_bounds__(256,2) out_gemm_b3(const float* __restrict__ Wo,
        const float* __restrict__ bo, float* __restrict__ outp){
    __shared__ unsigned Ah[2][1152], Al[2][1152];
    __shared__ unsigned Bh[2][1152], Bl[2][1152];
    int tid = threadIdx.x;
    int warp = tid >> 5, lane = tid & 31;
    int g = lane >> 2, tg = lane & 3;
    int wm = warp >> 2, wn = warp & 3;
    int m0 = blockIdx.y << 7, n0 = blockIdx.x << 7;

    float acc[4][4][4];
    #pragma unroll
    for (int a = 0; a < 4; a++)
        #pragma unroll
        for (int bq = 0; bq < 4; bq++)
            #pragma unroll
            for (int c = 0; c < 4; c++) acc[a][bq][c] = 0.f;

    #pragma unroll
    for (int l = 0; l < 2; l++){
        int id = tid + (l << 8);
        int row = id >> 2, kq = (id & 3) << 2, kp = (id & 3) << 1;
        int m = m0 + row; int b = m >> 10, li = m & 1023;
        int h = kq >> 6, dd = kq & 63;
        float4 a = *(const float4*)(g_ctx + (((b << 4) + h) << 16) + (li << 6) + dd);
        unsigned h0,l0,h1,l1;
        split2(a.x, a.y, h0, l0); split2(a.z, a.w, h1, l1);
        Ah[0][row*9 + kp] = h0; Ah[0][row*9 + kp + 1] = h1;
        Al[0][row*9 + kp] = l0; Al[0][row*9 + kp + 1] = l1;
        float4 bb = *(const float4*)(Wo + (n0 + row)*1024 + kq);
        split2(bb.x, bb.y, h0, l0); split2(bb.z, bb.w, h1, l1);
        Bh[0][row*9 + kp] = h0; Bh[0][row*9 + kp + 1] = h1;
        Bl[0][row*9 + kp] = l0; Bl[0][row*9 + kp + 1] = l1;
    }
    __syncthreads();

    int s = 0;
    for (int kt = 0; kt < 64; kt++){
        float4 pa[2], pb[2];
        if (kt < 63){
            int k0n = (kt + 1) << 4;
            #pragma unroll
            for (int l = 0; l < 2; l++){
                int id = tid + (l << 8);
                int row = id >> 2, kq = (id & 3) << 2;
                int m = m0 + row; int b = m >> 10, li = m & 1023;
                int k = k0n + kq; int h = k >> 6, dd = k & 63;
                pa[l] = *(const float4*)(g_ctx + (((b << 4) + h) << 16) + (li << 6) + dd);
                pb[l] = *(const float4*)(Wo + (n0 + row)*1024 + k0n + kq);
            }
        }

        unsigned bh[4][2], bl_[4][2];
        #pragma unroll
        for (int nt = 0; nt < 4; nt++){
            int nb = (wn << 5) + (nt << 3) + g;
            bh[nt][0]  = Bh[s][nb*9 + tg];     bh[nt][1]  = Bh[s][nb*9 + tg + 4];
            bl_[nt][0] = Bl[s][nb*9 + tg];     bl_[nt][1] = Bl[s][nb*9 + tg + 4];
        }
        #pragma unroll
        for (int mt = 0; mt < 4; mt++){
            int rb = (wm << 6) + (mt << 4);
            unsigned ah[4], al_[4];
            ah[0]  = Ah[s][(rb + g    )*9 + tg];     ah[1]  = Ah[s][(rb + g + 8)*9 + tg];
            ah[2]  = Ah[s][(rb + g    )*9 + tg + 4]; ah[3]  = Ah[s][(rb + g + 8)*9 + tg + 4];
            al_[0] = Al[s][(rb + g    )*9 + tg];     al_[1] = Al[s][(rb + g + 8)*9 + tg];
            al_[2] = Al[s][(rb + g    )*9 + tg + 4]; al_[3] = Al[s][(rb + g + 8)*9 + tg + 4];
            #pragma unroll
            for (int nt = 0; nt < 4; nt++){
                mma_bf16(acc[mt][nt], ah,  bh[nt]);
                mma_bf16(acc[mt][nt], ah,  bl_[nt]);
                mma_bf16(acc[mt][nt], al_, bh[nt]);
            }
        }

        if (kt < 63){
            #pragma unroll
            for (int l = 0; l < 2; l++){
                int id = tid + (l << 8);
                int row = id >> 2, kp = (id & 3) << 1;
                unsigned h0,l0,h1,l1;
                split2(pa[l].x, pa[l].y, h0, l0); split2(pa[l].z, pa[l].w, h1, l1);
                Ah[s^1][row*9 + kp] = h0; Ah[s^1][row*9 + kp + 1] = h1;
                Al[s^1][row*9 + kp] = l0; Al[s^1][row*9 + kp + 1] = l1;
                split2(pb[l].x, pb[l].y, h0, l0); split2(pb[l].z, pb[l].w, h1, l1);
                Bh[s^1][row*9 + kp] = h0; Bh[s^1][row*9 + kp + 1] = h1;
                Bl[s^1][row*9 + kp] = l0; Bl[s^1][row*9 + kp + 1] = l1;
            }
        }
        __syncthreads();
        s ^= 1;
    }

    #pragma unroll
    for (int mt = 0; mt < 4; mt++){
        #pragma unroll
        for (int nt = 0; nt < 4; nt++){
            int m = m0 + (wm << 6) + (mt << 4) + g;
            int n = n0 + (wn << 5) + (nt << 3) + (tg << 1);
            float b0v = bo[n], b1v = bo[n + 1];
            *(float2*)(outp + m*1024 + n) = make_float2(acc[mt][nt][0] + b0v, acc[mt][nt][1] + b1v);
            *(float2*)(outp + (m + 8)*1024 + n) = make_float2(acc[mt][nt][2] + b0v, acc[mt][nt][3] + b1v);
        }
    }
}

// ---------------------------------------------------------------------------
// Flash attention: 128x128 S tiles, 256 threads, 8x8 micro-tile (split 4+4).
// Q/K stored transposed (k-major) in smem -> conflict-free/broadcast LDS.128.
// ---------------------------------------------------------------------------
#define SQT 0                       // [64][132] floats
#define SKT (64*132)                // [64][132]
#define SVV (2*64*132)              // [128][68]
#define SPP (2*64*132 + 128*68)     // [128][132]
#define ATTN_SMEM ((2*64*132 + 128*68 + 128*132) * 4)

__global__ void __launch_bounds__(256) attn_kernel(const float* __restrict__ dist_bias){
    extern __shared__ float sm[];
    int b = blockIdx.z, h = blockIdx.y, it = blockIdx.x;
    int i0 = it << 7;
    int tid = threadIdx.x;
    int ty = tid >> 4, tx = tid & 15;
    const float* qb = g_q + (((b << 4) + h) << 16);
    const float* kb = g_k + (((b << 4) + h) << 16);
    const float* vb = g_v + (((b << 4) + h) << 16);
    const float* biasb = g_bias + (b << 20);
    float db = dist_bias[h];

    // stage Q transposed: sqT[kk][row]
    #pragma unroll
    for (int l = 0; l < 8; l++){
        int id = tid + (l << 8);
        int row = id >> 4, kq = (id & 15) << 2;
        float4 q4 = *(const float4*)(qb + ((i0 + row) << 6) + kq);
        sm[SQT + (kq+0)*132 + row] = q4.x;
        sm[SQT + (kq+1)*132 + row] = q4.y;
        sm[SQT + (kq+2)*132 + row] = q4.z;
        sm[SQT + (kq+3)*132 + row] = q4.w;
    }

    float m_r[8], l_r[8], acc[8][4];
    #pragma unroll
    for (int r = 0; r < 8; r++){
        m_r[r] = -INFINITY; l_r[r] = 0.f;
        #pragma unroll
        for (int c = 0; c < 4; c++) acc[r][c] = 0.f;
    }

    for (int jt = 0; jt < 8; jt++){
        int j0 = jt << 7;
        __syncthreads();
        #pragma unroll
        for (int l = 0; l < 8; l++){
            int id = tid + (l << 8);
            int row = id >> 4, kq = (id & 15) << 2;
            float4 k4 = *(const float4*)(kb + ((j0 + row) << 6) + kq);
            sm[SKT + (kq+0)*132 + row] = k4.x;
            sm[SKT + (kq+1)*132 + row] = k4.y;
            sm[SKT + (kq+2)*132 + row] = k4.z;
            sm[SKT + (kq+3)*132 + row] = k4.w;
            float4 v4 = *(const float4*)(vb + ((j0 + row) << 6) + kq);
            *(float4*)&sm[SVV + row*68 + kq] = v4;
        }

        float4 bf[8][2];
        #pragma unroll
        for (int rr = 0; rr < 8; rr++){
            int row = (ty << 2) + (rr & 3) + ((rr >> 2) << 6);
            const float* bp = biasb + ((i0 + row) << 10) + j0;
            bf[rr][0] = *(const float4*)(bp + (tx << 2));
            bf[rr][1] = *(const float4*)(bp + 64 + (tx << 2));
        }
        __syncthreads();

        float s[8][8];
        #pragma unroll
        for (int r = 0; r < 8; r++)
            #pragma unroll
            for (int c = 0; c < 8; c++) s[r][c] = 0.f;

        for (int kk = 0; kk < 64; kk++){
            float4 q0 = *(float4*)&sm[SQT + kk*132 + (ty << 2)];
            float4 q1 = *(float4*)&sm[SQT + kk*132 + 64 + (ty << 2)];
            float4 k0 = *(float4*)&sm[SKT + kk*132 + (tx << 2)];
            float4 k1 = *(float4*)&sm[SKT + kk*132 + 64 + (tx << 2)];
            float qv[8] = {q0.x,q0.y,q0.z,q0.w,q1.x,q1.y,q1.z,q1.w};
            float kv[8] = {k0.x,k0.y,k0.z,k0.w,k1.x,k1.y,k1.z,k1.w};
            #pragma unroll
            for (int r = 0; r < 8; r++)
                #pragma unroll
                for (int c = 0; c < 8; c++)
                    s[r][c] += qv[r] * kv[c];
        }

        #pragma unroll
        for (int rr = 0; rr < 8; rr++){
            float bv[8] = {bf[rr][0].x, bf[rr][0].y, bf[rr][0].z, bf[rr][0].w,
                           bf[rr][1].x, bf[rr][1].y, bf[rr][1].z, bf[rr][1].w};
            #pragma unroll
            for (int c = 0; c < 8; c++)
                s[rr][c] = s[rr][c]*0.125f + bv[c] + db;

            float mx = s[rr][0];
            #pragma unroll
            for (int c = 1; c < 8; c++) mx = fmaxf(mx, s[rr][c]);
            #pragma unroll
            for (int off = 1; off < 16; off <<= 1)
                mx = fmaxf(mx, __shfl_xor_sync(0xffffffffu, mx, off));
            float mnew = fmaxf(m_r[rr], mx);
            float corr = __expf(m_r[rr] - mnew);
            float psum = 0.f;
            #pragma unroll
            for (int c = 0; c < 8; c++){
                s[rr][c] = __expf(s[rr][c] - mnew);
                psum += s[rr][c];
            }
            #pragma unroll
            for (int off = 1; off < 16; off <<= 1)
                psum += __shfl_xor_sync(0xffffffffu, psum, off);
            l_r[rr] = l_r[rr]*corr + psum;
            m_r[rr] = mnew;
            #pragma unroll
            for (int c = 0; c < 4; c++) acc[rr][c] *= corr;

            int row = (ty << 2) + (rr & 3) + ((rr >> 2) << 6);
            *(float4*)&sm[SPP + row*132 + (tx << 2)] =
                make_float4(s[rr][0], s[rr][1], s[rr][2], s[rr][3]);
            *(float4*)&sm[SPP + row*132 + 64 + (tx << 2)] =
                make_float4(s[rr][4], s[rr][5], s[rr][6], s[rr][7]);
        }
        __syncthreads();

        for (int j4 = 0; j4 < 32; j4++){
            float4 vv[4];
            #pragma unroll
            for (int jj = 0; jj < 4; jj++)
                vv[jj] = *(float4*)&sm[SVV + ((j4 << 2) + jj)*68 + (tx << 2)];
            #pragma unroll
            for (int rr = 0; rr < 8; rr++){
                int row = (ty << 2) + (rr & 3) + ((rr >> 2) << 6);
                float4 pp = *(float4*)&sm[SPP + row*132 + (j4 << 2)];
                float pv[4] = {pp.x, pp.y, pp.z, pp.w};
                #pragma unroll
                for (int jj = 0; jj < 4; jj++){
                    acc[rr][0] += pv[jj] * vv[jj].x;
                    acc[rr][1] += pv[jj] * vv[jj].y;
                    acc[rr][2] += pv[jj] * vv[jj].z;
                    acc[rr][3] += pv[jj] * vv[jj].w;
                }
            }
        }
    }

    #pragma unroll
    for (int rr = 0; rr < 8; rr++){
        int row = (ty << 2) + (rr & 3) + ((rr >> 2) << 6);
        float inv = 1.f / l_r[rr];
        float4 o = make_float4(acc[rr][0]*inv, acc[rr][1]*inv, acc[rr][2]*inv, acc[rr][3]*inv);
        *(float4*)(g_ctx + (((b << 4) + h) << 16) + ((i0 + row) << 6) + (tx << 2)) = o;
    }
}

extern "C" void kernel_launch(void* const* d_in, const int* in_sizes, int n_in,
                              void* d_out, int out_size){
    const float* x         = (const float*)d_in[0];
    const float* pf        = (const float*)d_in[1];
    const int*   aa        = (const int*)  d_in[2];
    const float* ss        = (const float*)d_in[3];
    const float* Wq        = (const float*)d_in[4];
    const float* Wk        = (const float*)d_in[5];
    const float* Wv        = (const float*)d_in[6];
    const float* Wo        = (const float*)d_in[7];
    const float* bo        = (const float*)d_in[8];
    const float* dist_bias = (const float*)d_in[9];
    const float* inter_mat = (const float*)d_in[10];
    const float* ssw       = (const float*)d_in[11];
    const float* ps        = (const float*)d_in[12];
    const float* dd        = (const float*)d_in[13];
    float* out = (float*)d_out;

    proj_kernel<<<256, 256>>>(ss, ssw);
    bias_kernel<<<4096, 256>>>(pf, aa, inter_mat, ps, dd);

    dim3 gq(8, 32, 3);
    qkv_gemm_b3<<<gq, 256>>>(x, Wq, Wk, Wv);

    cudaFuncSetAttribute(attn_kernel, cudaFuncAttributeMaxDynamicSharedMemorySize, ATTN_SMEM);
    dim3 ga(8, 16, 4);
    attn_kernel<<<ga, 256, ATTN_SMEM>>>(dist_bias);

    dim3 go(8, 32, 1);
    out_gemm_b3<<<go, 256>>>(Wo, bo, out);
}

// round 9
// speedup vs baseline: 2.4207x; 1.3479x over previous
#include <cuda_runtime.h>
#include <cuda_bf16.h>
#include <math.h>

#define B_ 4
#define L_ 1024
#define H_ 16
#define DK 64

// Scratch (device globals; no allocation allowed)
__device__ float g_q[B_*H_*L_*DK];
__device__ float g_k[B_*H_*L_*DK];
__device__ float g_v[B_*H_*L_*DK];
__device__ float g_ctx[B_*H_*L_*DK];
__device__ float g_bias[B_*L_*L_];
__device__ float g_proj[B_*L_*H_];

__device__ __forceinline__ int clampi(int v, int lo, int hi){
    return v < lo ? lo : (v > hi ? hi : v);
}

// Split an fp32 pair into packed bf16x2 hi and lo words (x -> low half).
__device__ __forceinline__ void split2(float x, float y, unsigned& hiw, unsigned& low){
    __nv_bfloat16 hx = __float2bfloat16(x);
    __nv_bfloat16 hy = __float2bfloat16(y);
    float rx = x - __bfloat162float(hx);
    float ry = y - __bfloat162float(hy);
    __nv_bfloat162 h; h.x = hx; h.y = hy;
    __nv_bfloat162 l = __floats2bfloat162_rn(rx, ry);
    hiw = *(unsigned*)&h;
    low = *(unsigned*)&l;
}

// m16n8k16 bf16 mma, f32 accumulate
__device__ __forceinline__ void mma_bf16(float* c, const unsigned* a, const unsigned* b){
    asm volatile(
        "mma.sync.aligned.m16n8k16.row.col.f32.bf16.bf16.f32 "
        "{%0,%1,%2,%3},{%4,%5,%6,%7},{%8,%9},{%0,%1,%2,%3};"
        : "+f"(c[0]), "+f"(c[1]), "+f"(c[2]), "+f"(c[3])
        : "r"(a[0]), "r"(a[1]), "r"(a[2]), "r"(a[3]), "r"(b[0]), "r"(b[1]));
}

// proj[b,i,h] = sum_s ss[b,i,s] * ssw[h,s]
__global__ void proj_kernel(const float* __restrict__ ss, const float* __restrict__ ssw){
    int gid = blockIdx.x * 256 + threadIdx.x;   // B*L*H = 65536
    int ih = gid >> 4;
    int h  = gid & 15;
    float acc = 0.f;
    #pragma unroll
    for (int s = 0; s < 8; s++) acc += ss[ih*8 + s] * ssw[h*8 + s];
    g_proj[gid] = acc;
}

// bias_base[b,i,j] = dist_pen + inter + struct  (head-independent part)
__global__ void bias_kernel(const float* __restrict__ pf, const int* __restrict__ aa,
                            const float* __restrict__ inter_mat,
                            const float* __restrict__ ps_p, const float* __restrict__ dd_p){
    __shared__ float s_inter[625];
    __shared__ float s_pi[16];
    int tid = threadIdx.x;
    int bi = blockIdx.x;            // b*L + i
    int b = bi >> 10, i = bi & 1023;
    for (int t = tid; t < 625; t += 256) s_inter[t] = inter_mat[t];
    if (tid < 16) s_pi[tid] = g_proj[bi*16 + tid];
    __syncthreads();

    float sigps = 1.f / (1.f + __expf(-ps_p[0]));
    float decay = fminf(fmaxf(dd_p[0], 0.1f), 5.0f);
    int ai = clampi(aa[bi], 0, 24);
    float pi[16];
    #pragma unroll
    for (int s = 0; s < 16; s++) pi[s] = s_pi[s];
    const float* projb = g_proj + (b << 10) * 16;
    int base = (b << 20) + (i << 10);

    for (int jj = 0; jj < 4; jj++){
        int j = tid + (jj << 8);
        float d = pf[base + j];
        d = fminf(fmaxf(d, 0.1f), 50.0f);
        float pen = -__powf(d, decay) * sigps;
        int aj = clampi(aa[(b << 10) + j], 0, 24);
        float sym = 0.5f * (s_inter[ai*25 + aj] + s_inter[aj*25 + ai]);
        float interv = sym / (1.0f + fabsf((float)(j - i)));
        const float* pj = projb + j*16;
        float dot = 0.f;
        #pragma unroll
        for (int s = 0; s < 16; s++) dot += pi[s] * pj[s];
        float st = 1.f / (1.f + __expf(-dot)) - 0.5f;
        g_bias[base + j] = pen + interv + st;
    }
}

// ---------------------------------------------------------------------------
// bf16x3 tensor GEMM: C = x @ W^T, stored to (B,H,L,dk). (unchanged, known-good)
// ---------------------------------------------------------------------------
__global__ void __launch_bounds__(256,2) qkv_gemm_b3(const float* __restrict__ x,
        const float* __restrict__ Wq, const float* __restrict__ Wk, const float* __restrict__ Wv){
    __shared__ unsigned Ah[2][1152], Al[2][1152];   // 128 * 9
    __shared__ unsigned Bh[2][1152], Bl[2][1152];
    const float* W; float* out;
    if (blockIdx.z == 0)      { W = Wq; out = g_q; }
    else if (blockIdx.z == 1) { W = Wk; out = g_k; }
    else                      { W = Wv; out = g_v; }

    int tid = threadIdx.x;
    int warp = tid >> 5, lane = tid & 31;
    int g = lane >> 2, tg = lane & 3;
    int wm = warp >> 2, wn = warp & 3;
    int m0 = blockIdx.y << 7, n0 = blockIdx.x << 7;

    float acc[4][4][4];
    #pragma unroll
    for (int a = 0; a < 4; a++)
        #pragma unroll
        for (int bq = 0; bq < 4; bq++)
            #pragma unroll
            for (int c = 0; c < 4; c++) acc[a][bq][c] = 0.f;

    #pragma unroll
    for (int l = 0; l < 2; l++){
        int id = tid + (l << 8);
        int row = id >> 2, kq = (id & 3) << 2, kp = (id & 3) << 1;
        float4 a = *(const float4*)(x + (m0 + row)*1024 + kq);
        unsigned h0,l0,h1,l1;
        split2(a.x, a.y, h0, l0); split2(a.z, a.w, h1, l1);
        Ah[0][row*9 + kp] = h0; Ah[0][row*9 + kp + 1] = h1;
        Al[0][row*9 + kp] = l0; Al[0][row*9 + kp + 1] = l1;
        float4 bb = *(const float4*)(W + (n0 + row)*1024 + kq);
        split2(bb.x, bb.y, h0, l0); split2(bb.z, bb.w, h1, l1);
        Bh[0][row*9 + kp] = h0; Bh[0][row*9 + kp + 1] = h1;
        Bl[0][row*9 + kp] = l0; Bl[0][row*9 + kp + 1] = l1;
    }
    __syncthreads();

    int s = 0;
    for (int kt = 0; kt < 64; kt++){
        float4 pa[2], pb[2];
        if (kt < 63){
            int k0n = (kt + 1) << 4;
            #pragma unroll
            for (int l = 0; l < 2; l++){
                int id = tid + (l << 8);
                int row = id >> 2, kq = (id & 3) << 2;
                pa[l] = *(const float4*)(x + (m0 + row)*1024 + k0n + kq);
                pb[l] = *(const float4*)(W + (n0 + row)*1024 + k0n + kq);
            }
        }

        unsigned bh[4][2], bl_[4][2];
        #pragma unroll
        for (int nt = 0; nt < 4; nt++){
            int nb = (wn << 5) + (nt << 3) + g;
            bh[nt][0]  = Bh[s][nb*9 + tg];     bh[nt][1]  = Bh[s][nb*9 + tg + 4];
            bl_[nt][0] = Bl[s][nb*9 + tg];     bl_[nt][1] = Bl[s][nb*9 + tg + 4];
        }
        #pragma unroll
        for (int mt = 0; mt < 4; mt++){
            int rb = (wm << 6) + (mt << 4);
            unsigned ah[4], al_[4];
            ah[0]  = Ah[s][(rb + g    )*9 + tg];     ah[1]  = Ah[s][(rb + g + 8)*9 + tg];
            ah[2]  = Ah[s][(rb + g    )*9 + tg + 4]; ah[3]  = Ah[s][(rb + g + 8)*9 + tg + 4];
            al_[0] = Al[s][(rb + g    )*9 + tg];     al_[1] = Al[s][(rb + g + 8)*9 + tg];
            al_[2] = Al[s][(rb + g    )*9 + tg + 4]; al_[3] = Al[s][(rb + g + 8)*9 + tg + 4];
            #pragma unroll
            for (int nt = 0; nt < 4; nt++){
                mma_bf16(acc[mt][nt], ah,  bh[nt]);
                mma_bf16(acc[mt][nt], ah,  bl_[nt]);
                mma_bf16(acc[mt][nt], al_, bh[nt]);
            }
        }

        if (kt < 63){
            #pragma unroll
            for (int l = 0; l < 2; l++){
                int id = tid + (l << 8);
                int row = id >> 2, kp = (id & 3) << 1;
                unsigned h0,l0,h1,l1;
                split2(pa[l].x, pa[l].y, h0, l0); split2(pa[l].z, pa[l].w, h1, l1);
                Ah[s^1][row*9 + kp] = h0; Ah[s^1][row*9 + kp + 1] = h1;
                Al[s^1][row*9 + kp] = l0; Al[s^1][row*9 + kp + 1] = l1;
                split2(pb[l].x, pb[l].y, h0, l0); split2(pb[l].z, pb[l].w, h1, l1);
                Bh[s^1][row*9 + kp] = h0; Bh[s^1][row*9 + kp + 1] = h1;
                Bl[s^1][row*9 + kp] = l0; Bl[s^1][row*9 + kp + 1] = l1;
            }
        }
        __syncthreads();
        s ^= 1;
    }

    #pragma unroll
    for (int mt = 0; mt < 4; mt++){
        #pragma unroll
        for (int nt = 0; nt < 4; nt++){
            int m = m0 + (wm << 6) + (mt << 4) + g;
            int n = n0 + (wn << 5) + (nt << 3) + (tg << 1);
            int b = m >> 10, li = m & 1023;
            int h = n >> 6, dd = n & 63;
            float* p0 = out + ((((b << 4) + h) << 16) + (li << 6) + dd);
            *(float2*)p0 = make_float2(acc[mt][nt][0], acc[mt][nt][1]);
            float* p1 = out + ((((b << 4) + h) << 16) + ((li + 8) << 6) + dd);
            *(float2*)p1 = make_float2(acc[mt][nt][2], acc[mt][nt][3]);
        }
    }
}

// out = ctx @ Wo^T + bo  (unchanged, known-good)
__global__ void __launch_bounds__(256,2) out_gemm_b3(const float* __restrict__ Wo,
        const float* __restrict__ bo, float* __restrict__ outp){
    __shared__ unsigned Ah[2][1152], Al[2][1152];
    __shared__ unsigned Bh[2][1152], Bl[2][1152];
    int tid = threadIdx.x;
    int warp = tid >> 5, lane = tid & 31;
    int g = lane >> 2, tg = lane & 3;
    int wm = warp >> 2, wn = warp & 3;
    int m0 = blockIdx.y << 7, n0 = blockIdx.x << 7;

    float acc[4][4][4];
    #pragma unroll
    for (int a = 0; a < 4; a++)
        #pragma unroll
        for (int bq = 0; bq < 4; bq++)
            #pragma unroll
            for (int c = 0; c < 4; c++) acc[a][bq][c] = 0.f;

    #pragma unroll
    for (int l = 0; l < 2; l++){
        int id = tid + (l << 8);
        int row = id >> 2, kq = (id & 3) << 2, kp = (id & 3) << 1;
        int m = m0 + row; int b = m >> 10, li = m & 1023;
        int h = kq >> 6, dd = kq & 63;
        float4 a = *(const float4*)(g_ctx + (((b << 4) + h) << 16) + (li << 6) + dd);
        unsigned h0,l0,h1,l1;
        split2(a.x, a.y, h0, l0); split2(a.z, a.w, h1, l1);
        Ah[0][row*9 + kp] = h0; Ah[0][row*9 + kp + 1] = h1;
        Al[0][row*9 + kp] = l0; Al[0][row*9 + kp + 1] = l1;
        float4 bb = *(const float4*)(Wo + (n0 + row)*1024 + kq);
        split2(bb.x, bb.y, h0, l0); split2(bb.z, bb.w, h1, l1);
        Bh[0][row*9 + kp] = h0; Bh[0][row*9 + kp + 1] = h1;
        Bl[0][row*9 + kp] = l0; Bl[0][row*9 + kp + 1] = l1;
    }
    __syncthreads();

    int s = 0;
    for (int kt = 0; kt < 64; kt++){
        float4 pa[2], pb[2];
        if (kt < 63){
            int k0n = (kt + 1) << 4;
            #pragma unroll
            for (int l = 0; l < 2; l++){
                int id = tid + (l << 8);
                int row = id >> 2, kq = (id & 3) << 2;
                int m = m0 + row; int b = m >> 10, li = m & 1023;
                int k = k0n + kq; int h = k >> 6, dd = k & 63;
                pa[l] = *(const float4*)(g_ctx + (((b << 4) + h) << 16) + (li << 6) + dd);
                pb[l] = *(const float4*)(Wo + (n0 + row)*1024 + k0n + kq);
            }
        }

        unsigned bh[4][2], bl_[4][2];
        #pragma unroll
        for (int nt = 0; nt < 4; nt++){
            int nb = (wn << 5) + (nt << 3) + g;
            bh[nt][0]  = Bh[s][nb*9 + tg];     bh[nt][1]  = Bh[s][nb*9 + tg + 4];
            bl_[nt][0] = Bl[s][nb*9 + tg];     bl_[nt][1] = Bl[s][nb*9 + tg + 4];
        }
        #pragma unroll
        for (int mt = 0; mt < 4; mt++){
            int rb = (wm << 6) + (mt << 4);
            unsigned ah[4], al_[4];
            ah[0]  = Ah[s][(rb + g    )*9 + tg];     ah[1]  = Ah[s][(rb + g + 8)*9 + tg];
            ah[2]  = Ah[s][(rb + g    )*9 + tg + 4]; ah[3]  = Ah[s][(rb + g + 8)*9 + tg + 4];
            al_[0] = Al[s][(rb + g    )*9 + tg];     al_[1] = Al[s][(rb + g + 8)*9 + tg];
            al_[2] = Al[s][(rb + g    )*9 + tg + 4]; al_[3] = Al[s][(rb + g + 8)*9 + tg + 4];
            #pragma unroll
            for (int nt = 0; nt < 4; nt++){
                mma_bf16(acc[mt][nt], ah,  bh[nt]);
                mma_bf16(acc[mt][nt], ah,  bl_[nt]);
                mma_bf16(acc[mt][nt], al_, bh[nt]);
            }
        }

        if (kt < 63){
            #pragma unroll
            for (int l = 0; l < 2; l++){
                int id = tid + (l << 8);
                int row = id >> 2, kp = (id & 3) << 1;
                unsigned h0,l0,h1,l1;
                split2(pa[l].x, pa[l].y, h0, l0); split2(pa[l].z, pa[l].w, h1, l1);
                Ah[s^1][row*9 + kp] = h0; Ah[s^1][row*9 + kp + 1] = h1;
                Al[s^1][row*9 + kp] = l0; Al[s^1][row*9 + kp + 1] = l1;
                split2(pb[l].x, pb[l].y, h0, l0); split2(pb[l].z, pb[l].w, h1, l1);
                Bh[s^1][row*9 + kp] = h0; Bh[s^1][row*9 + kp + 1] = h1;
                Bl[s^1][row*9 + kp] = l0; Bl[s^1][row*9 + kp + 1] = l1;
            }
        }
        __syncthreads();
        s ^= 1;
    }

    #pragma unroll
    for (int mt = 0; mt < 4; mt++){
        #pragma unroll
        for (int nt = 0; nt < 4; nt++){
            int m = m0 + (wm << 6) + (mt << 4) + g;
            int n = n0 + (wn << 5) + (nt << 3) + (tg << 1);
            float b0v = bo[n], b1v = bo[n + 1];
            *(float2*)(outp + m*1024 + n) = make_float2(acc[mt][nt][0] + b0v, acc[mt][nt][1] + b1v);
            *(float2*)(outp + (m + 8)*1024 + n) = make_float2(acc[mt][nt][2] + b0v, acc[mt][nt][3] + b1v);
        }
    }
}

// ---------------------------------------------------------------------------
// MMA flash attention (bf16x3): 128-row Q tile per CTA, 8 warps x 16 rows.
// Q/K smem: [row][kpair] stride 36 (bank-perfect). V smem: j-pair packed
// [j/2][d] stride 68. P reused from S accumulators via register split.
// ---------------------------------------------------------------------------
#define AQS 36
#define AVS 68
#define SM_QH 0
#define SM_QL (128*AQS)
#define SM_KH (2*128*AQS)
#define SM_KL (3*128*AQS)
#define SM_VH (4*128*AQS)
#define SM_VL (4*128*AQS + 64*AVS)
#define ATTN_SMEM ((4*128*AQS + 2*64*AVS) * 4)

__global__ void __launch_bounds__(256,1) attn_mma(const float* __restrict__ dist_bias){
    extern __shared__ unsigned smw[];
    int b = blockIdx.z, h = blockIdx.y, it = blockIdx.x;
    int i0 = it << 7;
    int tid = threadIdx.x;
    int warp = tid >> 5, lane = tid & 31;
    int g = lane >> 2, tg = lane & 3;
    int rb = warp << 4;                       // warp's row base within tile
    const float* qb = g_q + (((b << 4) + h) << 16);
    const float* kb = g_k + (((b << 4) + h) << 16);
    const float* vb = g_v + (((b << 4) + h) << 16);
    const float* biasb = g_bias + (b << 20);
    float db = dist_bias[h];

    // stage Q (hi/lo) once: 128 rows x 16 float4s
    #pragma unroll
    for (int l = 0; l < 8; l++){
        int id = tid + (l << 8);
        int row = id >> 4, q4 = id & 15;
        float4 a = *(const float4*)(qb + ((i0 + row) << 6) + (q4 << 2));
        unsigned h0,l0,h1,l1;
        split2(a.x, a.y, h0, l0); split2(a.z, a.w, h1, l1);
        int o = row*AQS + (q4 << 1);
        smw[SM_QH + o] = h0; smw[SM_QH + o + 1] = h1;
        smw[SM_QL + o] = l0; smw[SM_QL + o + 1] = l1;
    }

    float m0 = -INFINITY, m1 = -INFINITY, l0s = 0.f, l1s = 0.f;
    float cacc[8][4];
    #pragma unroll
    for (int dt = 0; dt < 8; dt++)
        #pragma unroll
        for (int c = 0; c < 4; c++) cacc[dt][c] = 0.f;

    for (int jt = 0; jt < 8; jt++){
        int j0 = jt << 7;
        __syncthreads();
        // stage K (hi/lo)
        #pragma unroll
        for (int l = 0; l < 8; l++){
            int id = tid + (l << 8);
            int row = id >> 4, q4 = id & 15;
            float4 a = *(const float4*)(kb + ((j0 + row) << 6) + (q4 << 2));
            unsigned h0,l0,h1,l1;
            split2(a.x, a.y, h0, l0); split2(a.z, a.w, h1, l1);
            int o = row*AQS + (q4 << 1);
            smw[SM_KH + o] = h0; smw[SM_KH + o + 1] = h1;
            smw[SM_KL + o] = l0; smw[SM_KL + o + 1] = l1;
        }
        // stage V j-pair packed: word = (v[2jp][d], v[2jp+1][d])
        #pragma unroll
        for (int l = 0; l < 4; l++){
            int id = tid + (l << 8);
            int jp = id >> 4, dq = (id & 15) << 2;
            float4 va = *(const float4*)(vb + ((j0 + (jp << 1)) << 6) + dq);
            float4 vc = *(const float4*)(vb + ((j0 + (jp << 1) + 1) << 6) + dq);
            unsigned hw, lw;
            int o = jp*AVS + dq;
            split2(va.x, vc.x, hw, lw); smw[SM_VH + o    ] = hw; smw[SM_VL + o    ] = lw;
            split2(va.y, vc.y, hw, lw); smw[SM_VH + o + 1] = hw; smw[SM_VL + o + 1] = lw;
            split2(va.z, vc.z, hw, lw); smw[SM_VH + o + 2] = hw; smw[SM_VL + o + 2] = lw;
            split2(va.w, vc.w, hw, lw); smw[SM_VH + o + 3] = hw; smw[SM_VL + o + 3] = lw;
        }
        __syncthreads();

        // S = Q K^T : warp computes m16 x n128, k=64
        float sacc[16][4];
        #pragma unroll
        for (int nt = 0; nt < 16; nt++)
            #pragma unroll
            for (int c = 0; c < 4; c++) sacc[nt][c] = 0.f;

        #pragma unroll
        for (int ks = 0; ks < 4; ks++){
            unsigned ah[4], al_[4];
            int ro = (rb + g)*AQS + (ks << 3);
            int r1 = ro + 8*AQS;
            ah[0]  = smw[SM_QH + ro + tg];     ah[1]  = smw[SM_QH + r1 + tg];
            ah[2]  = smw[SM_QH + ro + 4 + tg]; ah[3]  = smw[SM_QH + r1 + 4 + tg];
            al_[0] = smw[SM_QL + ro + tg];     al_[1] = smw[SM_QL + r1 + tg];
            al_[2] = smw[SM_QL + ro + 4 + tg]; al_[3] = smw[SM_QL + r1 + 4 + tg];
            #pragma unroll
            for (int nt = 0; nt < 16; nt++){
                int ko = ((nt << 3) + g)*AQS + (ks << 3);
                unsigned bh[2], bl_[2];
                bh[0]  = smw[SM_KH + ko + tg]; bh[1]  = smw[SM_KH + ko + 4 + tg];
                bl_[0] = smw[SM_KL + ko + tg]; bl_[1] = smw[SM_KL + ko + 4 + tg];
                mma_bf16(sacc[nt], ah,  bh);
                mma_bf16(sacc[nt], ah,  bl_);
                mma_bf16(sacc[nt], al_, bh);
            }
        }

        // scale + bias (loads issued per-nt to keep live ranges short)
        int row0 = i0 + rb + g;
        const float* bp0 = biasb + (row0 << 10) + j0;
        const float* bp1 = biasb + ((row0 + 8) << 10) + j0;
        #pragma unroll
        for (int nt = 0; nt < 16; nt++){
            int col = (nt << 3) + (tg << 1);
            float2 b0 = *(const float2*)(bp0 + col);
            float2 b1 = *(const float2*)(bp1 + col);
            sacc[nt][0] = sacc[nt][0]*0.125f + b0.x + db;
            sacc[nt][1] = sacc[nt][1]*0.125f + b0.y + db;
            sacc[nt][2] = sacc[nt][2]*0.125f + b1.x + db;
            sacc[nt][3] = sacc[nt][3]*0.125f + b1.y + db;
        }

        // row max (quad reduce: row lives on 4 lanes with same g)
        float mx0 = -INFINITY, mx1 = -INFINITY;
        #pragma unroll
        for (int nt = 0; nt < 16; nt++){
            mx0 = fmaxf(mx0, fmaxf(sacc[nt][0], sacc[nt][1]));
            mx1 = fmaxf(mx1, fmaxf(sacc[nt][2], sacc[nt][3]));
        }
        mx0 = fmaxf(mx0, __shfl_xor_sync(0xffffffffu, mx0, 1));
        mx0 = fmaxf(mx0, __shfl_xor_sync(0xffffffffu, mx0, 2));
        mx1 = fmaxf(mx1, __shfl_xor_sync(0xffffffffu, mx1, 1));
        mx1 = fmaxf(mx1, __shfl_xor_sync(0xffffffffu, mx1, 2));

        float mn0 = fmaxf(m0, mx0), mn1 = fmaxf(m1, mx1);
        float cr0 = __expf(m0 - mn0), cr1 = __expf(m1 - mn1);
        float sum0 = 0.f, sum1 = 0.f;
        #pragma unroll
        for (int nt = 0; nt < 16; nt++){
            sacc[nt][0] = __expf(sacc[nt][0] - mn0);
            sacc[nt][1] = __expf(sacc[nt][1] - mn0);
            sacc[nt][2] = __expf(sacc[nt][2] - mn1);
            sacc[nt][3] = __expf(sacc[nt][3] - mn1);
            sum0 += sacc[nt][0] + sacc[nt][1];
            sum1 += sacc[nt][2] + sacc[nt][3];
        }
        sum0 += __shfl_xor_sync(0xffffffffu, sum0, 1);
        sum0 += __shfl_xor_sync(0xffffffffu, sum0, 2);
        sum1 += __shfl_xor_sync(0xffffffffu, sum1, 1);
        sum1 += __shfl_xor_sync(0xffffffffu, sum1, 2);
        l0s = l0s*cr0 + sum0;  m0 = mn0;
        l1s = l1s*cr1 + sum1;  m1 = mn1;
        #pragma unroll
        for (int dt = 0; dt < 8; dt++){
            cacc[dt][0] *= cr0; cacc[dt][1] *= cr0;
            cacc[dt][2] *= cr1; cacc[dt][3] *= cr1;
        }

        // ctx += P V : P from sacc (C-frag == A-frag), k = j (128 = 8 blocks of 16)
        #pragma unroll
        for (int jb = 0; jb < 8; jb++){
            unsigned aph[4], apl[4];
            split2(sacc[2*jb  ][0], sacc[2*jb  ][1], aph[0], apl[0]);
            split2(sacc[2*jb  ][2], sacc[2*jb  ][3], aph[1], apl[1]);
            split2(sacc[2*jb+1][0], sacc[2*jb+1][1], aph[2], apl[2]);
            split2(sacc[2*jb+1][2], sacc[2*jb+1][3], aph[3], apl[3]);
            #pragma unroll
            for (int dt = 0; dt < 8; dt++){
                int v0 = ((jb << 3) + tg)*AVS + (dt << 3) + g;
                int v1 = ((jb << 3) + 4 + tg)*AVS + (dt << 3) + g;
                unsigned bh[2], bl_[2];
                bh[0]  = smw[SM_VH + v0]; bh[1]  = smw[SM_VH + v1];
                bl_[0] = smw[SM_VL + v0]; bl_[1] = smw[SM_VL + v1];
                mma_bf16(cacc[dt], aph, bh);
                mma_bf16(cacc[dt], aph, bl_);
                mma_bf16(cacc[dt], apl, bh);
            }
        }
    }

    // write ctx
    float inv0 = 1.f / l0s, inv1 = 1.f / l1s;
    int row0 = i0 + rb + g;
    #pragma unroll
    for (int dt = 0; dt < 8; dt++){
        int dd = (dt << 3) + (tg << 1);
        float* p0 = g_ctx + ((((b << 4) + h) << 16) + (row0 << 6) + dd);
        *(float2*)p0 = make_float2(cacc[dt][0]*inv0, cacc[dt][1]*inv0);
        float* p1 = g_ctx + ((((b << 4) + h) << 16) + ((row0 + 8) << 6) + dd);
        *(float2*)p1 = make_float2(cacc[dt][2]*inv1, cacc[dt][3]*inv1);
    }
}

extern "C" void kernel_launch(void* const* d_in, const int* in_sizes, int n_in,
                              void* d_out, int out_size){
    const float* x         = (const float*)d_in[0];
    const float* pf        = (const float*)d_in[1];
    const int*   aa        = (const int*)  d_in[2];
    const float* ss        = (const float*)d_in[3];
    const float* Wq        = (const float*)d_in[4];
    const float* Wk        = (const float*)d_in[5];
    const float* Wv        = (const float*)d_in[6];
    const float* Wo        = (const float*)d_in[7];
    const float* bo        = (const float*)d_in[8];
    const float* dist_bias = (const float*)d_in[9];
    const float* inter_mat = (const float*)d_in[10];
    const float* ssw       = (const float*)d_in[11];
    const float* ps        = (const float*)d_in[12];
    const float* dd        = (const float*)d_in[13];
    float* out = (float*)d_out;

    proj_kernel<<<256, 256>>>(ss, ssw);
    bias_kernel<<<4096, 256>>>(pf, aa, inter_mat, ps, dd);

    dim3 gq(8, 32, 3);
    qkv_gemm_b3<<<gq, 256>>>(x, Wq, Wk, Wv);

    cudaFuncSetAttribute(attn_mma, cudaFuncAttributeMaxDynamicSharedMemorySize, ATTN_SMEM);
    dim3 ga(8, 16, 4);
    attn_mma<<<ga, 256, ATTN_SMEM>>>(dist_bias);

    dim3 go(8, 32, 1);
    out_gemm_b3<<<go, 256>>>(Wo, bo, out);
}